// round 15
// baseline (speedup 1.0000x reference)
#include <cuda_runtime.h>

// RNNModel: 2-layer tanh RNN + FC, B=2048, T=512, I=8, H=64.
// R14: tensor-core mma.m16n8k8.tf32 version, 8 elements/CTA, 4 warps.
// fp32 accuracy via hi/lo tf32 split (3 mma terms). W-hi regs, W-lo SMEM.
// pre-kernel: pre0 = s*(x.Wih0^T + b0) -> device scratch, used as C-init.
// Lag-1 layer pipeline, one __syncthreads per step.

#define BB 2048
#define TT 512
#define ECTA 8
#define NCTA (BB / ECTA)
#define SLOG 2.8853900817779268f   // 2*log2(e)
#define FULLMASK 0xffffffffu

typedef unsigned long long ull;

__device__ float g_pre[(size_t)NCTA * TT * 512 + 4096];   // 256MB + pad

__device__ __forceinline__ unsigned cvt_tf32(float f) {
    unsigned u; asm("cvt.rna.tf32.f32 %0, %1;" : "=r"(u) : "f"(f)); return u;
}
__device__ __forceinline__ void mma8(float& d0, float& d1, float& d2, float& d3,
                                     unsigned a0, unsigned a1, unsigned a2, unsigned a3,
                                     unsigned b0, unsigned b1) {
    asm volatile("mma.sync.aligned.m16n8k8.row.col.f32.tf32.tf32.f32 "
                 "{%0,%1,%2,%3},{%4,%5,%6,%7},{%8,%9},{%0,%1,%2,%3};"
                 : "+f"(d0), "+f"(d1), "+f"(d2), "+f"(d3)
                 : "r"(a0), "r"(a1), "r"(a2), "r"(a3), "r"(b0), "r"(b1));
}
__device__ __forceinline__ float fast_tanh_scaled(float zs) {
    float e; asm("ex2.approx.f32 %0, %1;" : "=f"(e) : "f"(zs));
    float r; asm("rcp.approx.f32 %0, %1;" : "=f"(r) : "f"(e + 1.f));
    return fmaf(-2.f, r, 1.f);
}

// ---------------- pre-kernel ----------------
__global__ void __launch_bounds__(512)
pre_kernel(const float* __restrict__ x, const float* __restrict__ W_ih0,
           const float* __restrict__ b_ih0, const float* __restrict__ b_hh0)
{
    const int ce = blockIdx.x >> 3, ts = blockIdx.x & 7;
    const int j = threadIdx.x >> 3, e = threadIdx.x & 7;
    const float* wr = W_ih0 + j * 8;
    float w0=wr[0],w1=wr[1],w2=wr[2],w3=wr[3],w4=wr[4],w5=wr[5],w6=wr[6],w7=wr[7];
    const float b = b_ih0[j] + b_hh0[j];
    const float4* xe = (const float4*)(x + (size_t)(ce*ECTA + e) * TT * 8);
    float* pe = g_pre + (size_t)ce * TT * 512;
    for (int t = ts*64; t < ts*64+64; t++) {
        float4 xa = xe[2*t], xb = xe[2*t+1];
        float s = b;
        s = fmaf(xa.x,w0,s); s = fmaf(xa.y,w1,s); s = fmaf(xa.z,w2,s); s = fmaf(xa.w,w3,s);
        s = fmaf(xb.x,w4,s); s = fmaf(xb.y,w5,s); s = fmaf(xb.z,w6,s); s = fmaf(xb.w,w7,s);
        pe[t*512 + threadIdx.x] = s * SLOG;     // layout [t][j*8+e]
    }
}

// ---------------- main kernel ----------------
extern __shared__ unsigned smu[];

__global__ void __launch_bounds__(128)
rnn_mma_kernel(const float* __restrict__ W_hh0, const float* __restrict__ W_ih1,
               const float* __restrict__ W_hh1, const float* __restrict__ b_ih1,
               const float* __restrict__ b_hh1, const float* __restrict__ fc_w,
               const float* __restrict__ fc_b, float* __restrict__ out)
{
    unsigned* WLO = smu;                   // 12288 uints (W-lo fragments)
    float* HBf = (float*)(smu + 12288);    // 8 buffers x 512 floats (h tf32 bits)
    float* SFC = HBf + 4096;               // 32 floats

    const int tid = threadIdx.x, w = tid >> 5, lane = tid & 31;
    const int g = lane >> 2, tt = lane & 3, mb = w * 16, ce = blockIdx.x;

    // h buffers: h0hi p0/p1 = 0/1, h0lo = 2/3, h1hi = 4/5, h1lo = 6/7.
    for (int i = tid; i < 4096; i += 128) HBf[i] = 0.f;

    // A-hi fragments (regs) + A-lo (SMEM). m16n8k8 A: rows g,g+8; cols tt,tt+4.
    unsigned Ah0[32], Ah1[32], Ah2[32];
#define BUILDW(AH, WP, MAT)                                                    \
    { _Pragma("unroll")                                                        \
      for (int t = 0; t < 8; t++) {                                            \
        int c0 = 8*t + tt, c1 = c0 + 4;                                        \
        float f0 = WP[(mb+g)*64 + c0] * SLOG;                                  \
        float f1 = WP[(mb+g+8)*64 + c0] * SLOG;                                \
        float f2 = WP[(mb+g)*64 + c1] * SLOG;                                  \
        float f3 = WP[(mb+g+8)*64 + c1] * SLOG;                                \
        unsigned u0=cvt_tf32(f0), u1=cvt_tf32(f1);                             \
        unsigned u2=cvt_tf32(f2), u3=cvt_tf32(f3);                             \
        AH[4*t]=u0; AH[4*t+1]=u1; AH[4*t+2]=u2; AH[4*t+3]=u3;                  \
        uint4 lo;                                                              \
        lo.x = cvt_tf32(f0 - __uint_as_float(u0));                             \
        lo.y = cvt_tf32(f1 - __uint_as_float(u1));                             \
        lo.z = cvt_tf32(f2 - __uint_as_float(u2));                             \
        lo.w = cvt_tf32(f3 - __uint_as_float(u3));                             \
        *(uint4*)&WLO[(((MAT)*4 + w)*8 + t)*128 + lane*4] = lo;                \
      } }
    BUILDW(Ah0, W_hh0, 0)
    BUILDW(Ah1, W_ih1, 1)
    BUILDW(Ah2, W_hh1, 2)
#undef BUILDW

    const float bj  = (b_ih1[mb+g]   + b_hh1[mb+g])   * SLOG;
    const float bj8 = (b_ih1[mb+g+8] + b_hh1[mb+g+8]) * SLOG;

    __syncthreads();

    // pre0 C-init fragment: c0,c1 = pre[row mb+g][e=2tt,2tt+1]; c2,c3 = row mb+g+8.
    const float2* pp = (const float2*)(g_pre + (size_t)ce * TT * 512) + (mb+g)*4 + tt;
    float2 cA = pp[0], cB = pp[32]; pp += 256;
    const int o = tt*8 + g;                       // B-fragment base: [k=tt][e=g]
    const int s0i = (mb+g)*8 + 2*tt, s1i = (mb+g+8)*8 + 2*tt;

#define SSTORE(V0, V1, V2, V3, BH, BL)                                         \
    { unsigned u0=cvt_tf32(V0), u1=cvt_tf32(V1);                               \
      unsigned u2=cvt_tf32(V2), u3=cvt_tf32(V3);                               \
      *(ull*)&HBf[(BH)*512 + s0i] = (ull)u0 | ((ull)u1 << 32);                 \
      *(ull*)&HBf[(BH)*512 + s1i] = (ull)u2 | ((ull)u3 << 32);                 \
      unsigned v0=cvt_tf32((V0)-__uint_as_float(u0));                          \
      unsigned v1=cvt_tf32((V1)-__uint_as_float(u1));                          \
      unsigned v2=cvt_tf32((V2)-__uint_as_float(u2));                          \
      unsigned v3=cvt_tf32((V3)-__uint_as_float(u3));                          \
      *(ull*)&HBf[(BL)*512 + s0i] = (ull)v0 | ((ull)v1 << 32);                 \
      *(ull*)&HBf[(BL)*512 + s1i] = (ull)v2 | ((ull)v3 << 32);                 \
    }

    // ---- Peel i=0: h0[0] = tanh(pre0[0]) (h0[-1]=0) -> parity-0 bufs ----
    {
        float h00=fast_tanh_scaled(cA.x), h01=fast_tanh_scaled(cA.y);
        float h02=fast_tanh_scaled(cB.x), h03=fast_tanh_scaled(cB.y);
        SSTORE(h00,h01,h02,h03, 0, 2)
        cA = pp[0]; cB = pp[32]; pp += 256;
        __syncthreads();
    }

    float h10, h11, h12, h13;

#define MMA3(D0,D1,D2,D3, AH, AL, BH0,BH1, BL0,BL1)                            \
    mma8(D0,D1,D2,D3, (AH)[0],(AH)[1],(AH)[2],(AH)[3], BH0,BH1);               \
    mma8(D0,D1,D2,D3, (AH)[0],(AH)[1],(AH)[2],(AH)[3], BL0,BL1);               \
    mma8(D0,D1,D2,D3, (AL).x,(AL).y,(AL).z,(AL).w, BH0,BH1);

    // STEP at iter i: h0[i] = tanh(pre[i] + s*Whh0.h0[i-1]),
    //                 h1[i-1] = tanh(s*b1 + s*Wih1.h0[i-1] + s*Whh1.h1[i-2]).
#define STEP(R0H,R0L,R1H,R1L, W0H,W0L,W1H,W1L)                                 \
    {                                                                          \
        float2 nA = pp[0], nB = pp[32]; pp += 256;                             \
        float d0a0=cA.x,d0a1=cA.y,d0a2=cB.x,d0a3=cB.y;                         \
        float d0b0=0,d0b1=0,d0b2=0,d0b3=0;                                     \
        float d1a0=bj,d1a1=bj,d1a2=bj8,d1a3=bj8;                               \
        float d1b0=0,d1b1=0,d1b2=0,d1b3=0;                                     \
        float d1c0=0,d1c1=0,d1c2=0,d1c3=0;                                     \
        float d1d0=0,d1d1=0,d1d2=0,d1d3=0;                                     \
        const float* B0h = HBf + (R0H)*512; const float* B0l = HBf + (R0L)*512;\
        const float* B1h = HBf + (R1H)*512; const float* B1l = HBf + (R1L)*512;\
        _Pragma("unroll")                                                      \
        for (int t = 0; t < 8; t++) {                                          \
            unsigned bh0=__float_as_uint(B0h[o+64*t]);                         \
            unsigned bh1=__float_as_uint(B0h[o+64*t+32]);                      \
            unsigned bl0=__float_as_uint(B0l[o+64*t]);                         \
            unsigned bl1=__float_as_uint(B0l[o+64*t+32]);                      \
            uint4 l0 = *(const uint4*)&WLO[((0+w)*8+t)*128 + lane*4];          \
            uint4 l1 = *(const uint4*)&WLO[((4+w)*8+t)*128 + lane*4];          \
            if ((t & 1) == 0) {                                                \
                MMA3(d0a0,d0a1,d0a2,d0a3, &Ah0[4*t], l0, bh0,bh1, bl0,bl1)     \
                MMA3(d1a0,d1a1,d1a2,d1a3, &Ah1[4*t], l1, bh0,bh1, bl0,bl1)     \
            } else {                                                           \
                MMA3(d0b0,d0b1,d0b2,d0b3, &Ah0[4*t], l0, bh0,bh1, bl0,bl1)     \
                MMA3(d1b0,d1b1,d1b2,d1b3, &Ah1[4*t], l1, bh0,bh1, bl0,bl1)     \
            }                                                                  \
        }                                                                      \
        _Pragma("unroll")                                                      \
        for (int t = 0; t < 8; t++) {                                          \
            unsigned bh0=__float_as_uint(B1h[o+64*t]);                         \
            unsigned bh1=__float_as_uint(B1h[o+64*t+32]);                      \
            unsigned bl0=__float_as_uint(B1l[o+64*t]);                         \
            unsigned bl1=__float_as_uint(B1l[o+64*t+32]);                      \
            uint4 l2 = *(const uint4*)&WLO[((8+w)*8+t)*128 + lane*4];          \
            if ((t & 1) == 0) {                                                \
                MMA3(d1c0,d1c1,d1c2,d1c3, &Ah2[4*t], l2, bh0,bh1, bl0,bl1)     \
            } else {                                                           \
                MMA3(d1d0,d1d1,d1d2,d1d3, &Ah2[4*t], l2, bh0,bh1, bl0,bl1)     \
            }                                                                  \
        }                                                                      \
        float h00=fast_tanh_scaled(d0a0+d0b0), h01=fast_tanh_scaled(d0a1+d0b1);\
        float h02=fast_tanh_scaled(d0a2+d0b2), h03=fast_tanh_scaled(d0a3+d0b3);\
        h10=fast_tanh_scaled(d1a0+d1b0+d1c0+d1d0);                             \
        h11=fast_tanh_scaled(d1a1+d1b1+d1c1+d1d1);                             \
        h12=fast_tanh_scaled(d1a2+d1b2+d1c2+d1d2);                             \
        h13=fast_tanh_scaled(d1a3+d1b3+d1c3+d1d3);                             \
        SSTORE(h00,h01,h02,h03, W0H, W0L)                                      \
        SSTORE(h10,h11,h12,h13, W1H, W1L)                                      \
        __syncthreads();                                                       \
        cA = nA; cB = nB;                                                      \
    }

    // i = 1..510 as 255 pairs, then i = 511.
    for (int it = 0; it < 255; it++) {
        STEP(0,2,5,7, 1,3,4,6)    // i odd:  h0r p0, h1r p1 -> h0 p1, h1 p0
        STEP(1,3,4,6, 0,2,5,7)    // i even: h0r p1, h1r p0 -> h0 p0, h1 p1
    }
    STEP(0,2,5,7, 1,3,4,6)        // i = 511
#undef STEP

    // ---- Tail i=512: h1[511] from h0[511] (bufs 1,3) and h1[510] (bufs 4,6) ----
    {
        float e1a0=bj,e1a1=bj,e1a2=bj8,e1a3=bj8;
        float e1b0=0,e1b1=0,e1b2=0,e1b3=0;
        float e1c0=0,e1c1=0,e1c2=0,e1c3=0;
        float e1d0=0,e1d1=0,e1d2=0,e1d3=0;
        const float* B0h = HBf + 512;   const float* B0l = HBf + 3*512;
        const float* B1h = HBf + 4*512; const float* B1l = HBf + 6*512;
        #pragma unroll
        for (int t = 0; t < 8; t++) {
            unsigned bh0=__float_as_uint(B0h[o+64*t]);
            unsigned bh1=__float_as_uint(B0h[o+64*t+32]);
            unsigned bl0=__float_as_uint(B0l[o+64*t]);
            unsigned bl1=__float_as_uint(B0l[o+64*t+32]);
            uint4 l1 = *(const uint4*)&WLO[((4+w)*8+t)*128 + lane*4];
            if ((t&1)==0) { MMA3(e1a0,e1a1,e1a2,e1a3, &Ah1[4*t], l1, bh0,bh1, bl0,bl1) }
            else          { MMA3(e1b0,e1b1,e1b2,e1b3, &Ah1[4*t], l1, bh0,bh1, bl0,bl1) }
        }
        #pragma unroll
        for (int t = 0; t < 8; t++) {
            unsigned bh0=__float_as_uint(B1h[o+64*t]);
            unsigned bh1=__float_as_uint(B1h[o+64*t+32]);
            unsigned bl0=__float_as_uint(B1l[o+64*t]);
            unsigned bl1=__float_as_uint(B1l[o+64*t+32]);
            uint4 l2 = *(const uint4*)&WLO[((8+w)*8+t)*128 + lane*4];
            if ((t&1)==0) { MMA3(e1c0,e1c1,e1c2,e1c3, &Ah2[4*t], l2, bh0,bh1, bl0,bl1) }
            else          { MMA3(e1d0,e1d1,e1d2,e1d3, &Ah2[4*t], l2, bh0,bh1, bl0,bl1) }
        }
        h10 = fast_tanh_scaled(e1a0+e1b0+e1c0+e1d0);
        h11 = fast_tanh_scaled(e1a1+e1b1+e1c1+e1d1);
        h12 = fast_tanh_scaled(e1a2+e1b2+e1c2+e1d2);
        h13 = fast_tanh_scaled(e1a3+e1b3+e1c3+e1d3);
    }
#undef MMA3
#undef SSTORE

    // ---- FC: out[ce*8+e] = sum_j h1[511][j]*fc_w[j] + fc_b ----
    {
        float fw0 = fc_w[mb+g], fw8 = fc_w[mb+g+8];
        float p0 = h10*fw0 + h12*fw8;        // element e = 2tt
        float p1 = h11*fw0 + h13*fw8;        // element e = 2tt+1
        p0 += __shfl_xor_sync(FULLMASK,p0,4);  p1 += __shfl_xor_sync(FULLMASK,p1,4);
        p0 += __shfl_xor_sync(FULLMASK,p0,8);  p1 += __shfl_xor_sync(FULLMASK,p1,8);
        p0 += __shfl_xor_sync(FULLMASK,p0,16); p1 += __shfl_xor_sync(FULLMASK,p1,16);
        if (g == 0) { SFC[w*8 + 2*tt] = p0; SFC[w*8 + 2*tt + 1] = p1; }
        __syncthreads();
        if (tid < 8)
            out[ce*8 + tid] = SFC[tid] + SFC[8+tid] + SFC[16+tid] + SFC[24+tid] + fc_b[0];
    }
}

extern "C" void kernel_launch(void* const* d_in, const int* in_sizes, int n_in,
                              void* d_out, int out_size)
{
    const float* x     = (const float*)d_in[0];
    const float* W_ih0 = (const float*)d_in[1];
    const float* W_hh0 = (const float*)d_in[2];
    const float* b_ih0 = (const float*)d_in[3];
    const float* b_hh0 = (const float*)d_in[4];
    const float* W_ih1 = (const float*)d_in[5];
    const float* W_hh1 = (const float*)d_in[6];
    const float* b_ih1 = (const float*)d_in[7];
    const float* b_hh1 = (const float*)d_in[8];
    const float* fc_w  = (const float*)d_in[9];
    const float* fc_b  = (const float*)d_in[10];
    float* out = (float*)d_out;

    const int smem_bytes = (12288 + 4096 + 32) * 4;   // 65664
    cudaFuncSetAttribute(rnn_mma_kernel,
                         cudaFuncAttributeMaxDynamicSharedMemorySize, smem_bytes);

    pre_kernel<<<NCTA * 8, 512>>>(x, W_ih0, b_ih0, b_hh0);
    rnn_mma_kernel<<<NCTA, 128, smem_bytes>>>(W_hh0, W_ih1, W_hh1,
                                              b_ih1, b_hh1, fc_w, fc_b, out);
}

// round 16
// speedup vs baseline: 1.7431x; 1.7431x over previous
#include <cuda_runtime.h>

// RNNModel: 2-layer tanh RNN + FC, B=2048, T=512, I=8, H=64.
// R15: R14 tensor-core kernel with the pre-kernel/scratch ELIMINATED.
//  - x-projection computed inline: 32 scalar FFMA/thread/step on the idle fma
//    pipe, x staged via a 2-buffer SMEM tile (8 rows x 12-float stride,
//    conflict-free LDS; 16 threads prefetch 256B one step ahead).
//  - Everything else identical to the R14 kernel that passed (rel_err 7.5e-7):
//    mma.m16n8k8.tf32, hi/lo split (3 mma terms), W-hi regs, W-lo SMEM,
//    lag-1 layer pipeline, one __syncthreads per step.

#define BB 2048
#define TT 512
#define ECTA 8
#define NCTA (BB / ECTA)
#define SLOG 2.8853900817779268f   // 2*log2(e)
#define FULLMASK 0xffffffffu

typedef unsigned long long ull;

__device__ __forceinline__ unsigned cvt_tf32(float f) {
    unsigned u; asm("cvt.rna.tf32.f32 %0, %1;" : "=r"(u) : "f"(f)); return u;
}
__device__ __forceinline__ void mma8(float& d0, float& d1, float& d2, float& d3,
                                     unsigned a0, unsigned a1, unsigned a2, unsigned a3,
                                     unsigned b0, unsigned b1) {
    asm volatile("mma.sync.aligned.m16n8k8.row.col.f32.tf32.tf32.f32 "
                 "{%0,%1,%2,%3},{%4,%5,%6,%7},{%8,%9},{%0,%1,%2,%3};"
                 : "+f"(d0), "+f"(d1), "+f"(d2), "+f"(d3)
                 : "r"(a0), "r"(a1), "r"(a2), "r"(a3), "r"(b0), "r"(b1));
}
__device__ __forceinline__ float fast_tanh_scaled(float zs) {
    float e; asm("ex2.approx.f32 %0, %1;" : "=f"(e) : "f"(zs));
    float r; asm("rcp.approx.f32 %0, %1;" : "=f"(r) : "f"(e + 1.f));
    return fmaf(-2.f, r, 1.f);
}

extern __shared__ unsigned smu[];

__global__ void __launch_bounds__(128)
rnn_mma2_kernel(const float* __restrict__ x,
                const float* __restrict__ W_ih0, const float* __restrict__ W_hh0,
                const float* __restrict__ W_ih1, const float* __restrict__ W_hh1,
                const float* __restrict__ b_ih0, const float* __restrict__ b_hh0,
                const float* __restrict__ b_ih1, const float* __restrict__ b_hh1,
                const float* __restrict__ fc_w, const float* __restrict__ fc_b,
                float* __restrict__ out)
{
    unsigned* WLO = smu;                   // 12288 uints (W-lo fragments)
    float* HBf = (float*)(smu + 12288);    // 8 buffers x 512 floats (h tf32 bits)
    float* SFC = HBf + 4096;               // 32 floats
    float* SXF = SFC + 32;                 // 2 x-buffers x 96 floats (8 rows x 12)

    const int tid = threadIdx.x, w = tid >> 5, lane = tid & 31;
    const int g = lane >> 2, tt = lane & 3, mb = w * 16, ce = blockIdx.x;

    for (int i = tid; i < 4096; i += 128) HBf[i] = 0.f;

    // A-hi fragments (regs) + A-lo (SMEM). m16n8k8 A: rows g,g+8; cols tt,tt+4.
    unsigned Ah0[32], Ah1[32], Ah2[32];
#define BUILDW(AH, WP, MAT)                                                    \
    { _Pragma("unroll")                                                        \
      for (int t = 0; t < 8; t++) {                                            \
        int c0 = 8*t + tt, c1 = c0 + 4;                                        \
        float f0 = WP[(mb+g)*64 + c0] * SLOG;                                  \
        float f1 = WP[(mb+g+8)*64 + c0] * SLOG;                                \
        float f2 = WP[(mb+g)*64 + c1] * SLOG;                                  \
        float f3 = WP[(mb+g+8)*64 + c1] * SLOG;                                \
        unsigned u0=cvt_tf32(f0), u1=cvt_tf32(f1);                             \
        unsigned u2=cvt_tf32(f2), u3=cvt_tf32(f3);                             \
        AH[4*t]=u0; AH[4*t+1]=u1; AH[4*t+2]=u2; AH[4*t+3]=u3;                  \
        uint4 lo;                                                              \
        lo.x = cvt_tf32(f0 - __uint_as_float(u0));                             \
        lo.y = cvt_tf32(f1 - __uint_as_float(u1));                             \
        lo.z = cvt_tf32(f2 - __uint_as_float(u2));                             \
        lo.w = cvt_tf32(f3 - __uint_as_float(u3));                             \
        *(uint4*)&WLO[(((MAT)*4 + w)*8 + t)*128 + lane*4] = lo;                \
      } }
    BUILDW(Ah0, W_hh0, 0)
    BUILDW(Ah1, W_ih1, 1)
    BUILDW(Ah2, W_hh1, 2)
#undef BUILDW

    // W_ih0 rows (scaled) + biases for the inline x-projection.
    float w0g[8], w0g8[8];
    #pragma unroll
    for (int k = 0; k < 8; k++) {
        w0g[k]  = W_ih0[(mb+g)*8 + k]   * SLOG;
        w0g8[k] = W_ih0[(mb+g+8)*8 + k] * SLOG;
    }
    const float b0g  = (b_ih0[mb+g]   + b_hh0[mb+g])   * SLOG;
    const float b0g8 = (b_ih0[mb+g+8] + b_hh0[mb+g+8]) * SLOG;
    const float bj   = (b_ih1[mb+g]   + b_hh1[mb+g])   * SLOG;
    const float bj8  = (b_ih1[mb+g+8] + b_hh1[mb+g+8]) * SLOG;

    // x prefetch setup: threads 0..15 each own (element pe, half ph).
    const int pe = tid >> 1, ph = tid & 1;
    const float* xpf = x + ((size_t)(ce*ECTA + pe) * TT) * 8 + ph * 4;
    const int spfo = pe * 12 + ph * 4;
    if (tid < 16) *(float4*)&SXF[spfo] = *(const float4*)xpf;   // x[0] -> buf0
    xpf += 8;                                                   // -> x[1]

    __syncthreads();

    const int o = tt*8 + g;                       // B-fragment base: [k=tt][e=g]
    const int s0i = (mb+g)*8 + 2*tt, s1i = (mb+g+8)*8 + 2*tt;
    const int sxe0 = tt * 24;                     // row e0=2tt (12-float stride)

#define SSTORE(V0, V1, V2, V3, BH, BL)                                         \
    { unsigned u0=cvt_tf32(V0), u1=cvt_tf32(V1);                               \
      unsigned u2=cvt_tf32(V2), u3=cvt_tf32(V3);                               \
      *(ull*)&HBf[(BH)*512 + s0i] = (ull)u0 | ((ull)u1 << 32);                 \
      *(ull*)&HBf[(BH)*512 + s1i] = (ull)u2 | ((ull)u3 << 32);                 \
      unsigned v0=cvt_tf32((V0)-__uint_as_float(u0));                          \
      unsigned v1=cvt_tf32((V1)-__uint_as_float(u1));                          \
      unsigned v2=cvt_tf32((V2)-__uint_as_float(u2));                          \
      unsigned v3=cvt_tf32((V3)-__uint_as_float(u3));                          \
      *(ull*)&HBf[(BL)*512 + s0i] = (ull)v0 | ((ull)v1 << 32);                 \
      *(ull*)&HBf[(BL)*512 + s1i] = (ull)v2 | ((ull)v3 << 32);                 \
    }

    // Inline x-projection: r0..r3 = pre[t] C-fragment for this thread.
#define XDOT(CUR, R0, R1, R2, R3)                                              \
    {                                                                          \
        const float* sx = SXF + (CUR) * 96 + sxe0;                             \
        float4 a0 = *(const float4*)(sx);                                      \
        float4 a1 = *(const float4*)(sx + 4);                                  \
        float4 bb0 = *(const float4*)(sx + 12);                                \
        float4 bb1 = *(const float4*)(sx + 16);                                \
        R0 = b0g;  R1 = b0g;  R2 = b0g8; R3 = b0g8;                            \
        R0 = fmaf(a0.x,w0g[0],R0); R0 = fmaf(a0.y,w0g[1],R0);                  \
        R0 = fmaf(a0.z,w0g[2],R0); R0 = fmaf(a0.w,w0g[3],R0);                  \
        R0 = fmaf(a1.x,w0g[4],R0); R0 = fmaf(a1.y,w0g[5],R0);                  \
        R0 = fmaf(a1.z,w0g[6],R0); R0 = fmaf(a1.w,w0g[7],R0);                  \
        R1 = fmaf(bb0.x,w0g[0],R1); R1 = fmaf(bb0.y,w0g[1],R1);                \
        R1 = fmaf(bb0.z,w0g[2],R1); R1 = fmaf(bb0.w,w0g[3],R1);                \
        R1 = fmaf(bb1.x,w0g[4],R1); R1 = fmaf(bb1.y,w0g[5],R1);                \
        R1 = fmaf(bb1.z,w0g[6],R1); R1 = fmaf(bb1.w,w0g[7],R1);                \
        R2 = fmaf(a0.x,w0g8[0],R2); R2 = fmaf(a0.y,w0g8[1],R2);                \
        R2 = fmaf(a0.z,w0g8[2],R2); R2 = fmaf(a0.w,w0g8[3],R2);                \
        R2 = fmaf(a1.x,w0g8[4],R2); R2 = fmaf(a1.y,w0g8[5],R2);                \
        R2 = fmaf(a1.z,w0g8[6],R2); R2 = fmaf(a1.w,w0g8[7],R2);                \
        R3 = fmaf(bb0.x,w0g8[0],R3); R3 = fmaf(bb0.y,w0g8[1],R3);              \
        R3 = fmaf(bb0.z,w0g8[2],R3); R3 = fmaf(bb0.w,w0g8[3],R3);              \
        R3 = fmaf(bb1.x,w0g8[4],R3); R3 = fmaf(bb1.y,w0g8[5],R3);              \
        R3 = fmaf(bb1.z,w0g8[6],R3); R3 = fmaf(bb1.w,w0g8[7],R3);              \
    }

#define XPREF(NXT)                                                             \
    if (tid < 16) { *(float4*)&SXF[(NXT)*96 + spfo] = *(const float4*)xpf; }   \
    xpf += 8;

    // ---- Peel i=0: h0[0] = tanh(pre[0]) (h0[-1]=0) -> parity-0 bufs ----
    {
        float p0, p1, p2, p3;
        XDOT(0, p0, p1, p2, p3)
        XPREF(1)                               // x[1] -> buf1
        float h00=fast_tanh_scaled(p0), h01=fast_tanh_scaled(p1);
        float h02=fast_tanh_scaled(p2), h03=fast_tanh_scaled(p3);
        SSTORE(h00,h01,h02,h03, 0, 2)
        __syncthreads();
    }

    float h10, h11, h12, h13;

#define MMA3(D0,D1,D2,D3, AH, AL, BH0,BH1, BL0,BL1)                            \
    mma8(D0,D1,D2,D3, (AH)[0],(AH)[1],(AH)[2],(AH)[3], BH0,BH1);               \
    mma8(D0,D1,D2,D3, (AH)[0],(AH)[1],(AH)[2],(AH)[3], BL0,BL1);               \
    mma8(D0,D1,D2,D3, (AL).x,(AL).y,(AL).z,(AL).w, BH0,BH1);

    // STEP at iter i: h0[i] = tanh(pre[i] + s*Whh0.h0[i-1]),
    //                 h1[i-1] = tanh(s*b1 + s*Wih1.h0[i-1] + s*Whh1.h1[i-2]).
#define STEP(R0H,R0L,R1H,R1L, W0H,W0L,W1H,W1L, CUR, NXT, PF)                   \
    {                                                                          \
        float d0a0, d0a1, d0a2, d0a3;                                          \
        XDOT(CUR, d0a0, d0a1, d0a2, d0a3)                                      \
        if (PF) { XPREF(NXT) }                                                 \
        float d0b0=0,d0b1=0,d0b2=0,d0b3=0;                                     \
        float d1a0=bj,d1a1=bj,d1a2=bj8,d1a3=bj8;                               \
        float d1b0=0,d1b1=0,d1b2=0,d1b3=0;                                     \
        float d1c0=0,d1c1=0,d1c2=0,d1c3=0;                                     \
        float d1d0=0,d1d1=0,d1d2=0,d1d3=0;                                     \
        const float* B0h = HBf + (R0H)*512; const float* B0l = HBf + (R0L)*512;\
        const float* B1h = HBf + (R1H)*512; const float* B1l = HBf + (R1L)*512;\
        _Pragma("unroll")                                                      \
        for (int t = 0; t < 8; t++) {                                          \
            unsigned bh0=__float_as_uint(B0h[o+64*t]);                         \
            unsigned bh1=__float_as_uint(B0h[o+64*t+32]);                      \
            unsigned bl0=__float_as_uint(B0l[o+64*t]);                         \
            unsigned bl1=__float_as_uint(B0l[o+64*t+32]);                      \
            uint4 l0 = *(const uint4*)&WLO[((0+w)*8+t)*128 + lane*4];          \
            uint4 l1 = *(const uint4*)&WLO[((4+w)*8+t)*128 + lane*4];          \
            if ((t & 1) == 0) {                                                \
                MMA3(d0a0,d0a1,d0a2,d0a3, &Ah0[4*t], l0, bh0,bh1, bl0,bl1)     \
                MMA3(d1a0,d1a1,d1a2,d1a3, &Ah1[4*t], l1, bh0,bh1, bl0,bl1)     \
            } else {                                                           \
                MMA3(d0b0,d0b1,d0b2,d0b3, &Ah0[4*t], l0, bh0,bh1, bl0,bl1)     \
                MMA3(d1b0,d1b1,d1b2,d1b3, &Ah1[4*t], l1, bh0,bh1, bl0,bl1)     \
            }                                                                  \
        }                                                                      \
        _Pragma("unroll")                                                      \
        for (int t = 0; t < 8; t++) {                                          \
            unsigned bh0=__float_as_uint(B1h[o+64*t]);                         \
            unsigned bh1=__float_as_uint(B1h[o+64*t+32]);                      \
            unsigned bl0=__float_as_uint(B1l[o+64*t]);                         \
            unsigned bl1=__float_as_uint(B1l[o+64*t+32]);                      \
            uint4 l2 = *(const uint4*)&WLO[((8+w)*8+t)*128 + lane*4];          \
            if ((t & 1) == 0) {                                                \
                MMA3(d1c0,d1c1,d1c2,d1c3, &Ah2[4*t], l2, bh0,bh1, bl0,bl1)     \
            } else {                                                           \
                MMA3(d1d0,d1d1,d1d2,d1d3, &Ah2[4*t], l2, bh0,bh1, bl0,bl1)     \
            }                                                                  \
        }                                                                      \
        float h00=fast_tanh_scaled(d0a0+d0b0), h01=fast_tanh_scaled(d0a1+d0b1);\
        float h02=fast_tanh_scaled(d0a2+d0b2), h03=fast_tanh_scaled(d0a3+d0b3);\
        h10=fast_tanh_scaled(d1a0+d1b0+d1c0+d1d0);                             \
        h11=fast_tanh_scaled(d1a1+d1b1+d1c1+d1d1);                             \
        h12=fast_tanh_scaled(d1a2+d1b2+d1c2+d1d2);                             \
        h13=fast_tanh_scaled(d1a3+d1b3+d1c3+d1d3);                             \
        SSTORE(h00,h01,h02,h03, W0H, W0L)                                      \
        SSTORE(h10,h11,h12,h13, W1H, W1L)                                      \
        __syncthreads();                                                       \
    }

    // i = 1..510 as 255 pairs, then i = 511.
    for (int it = 0; it < 255; it++) {
        STEP(0,2,5,7, 1,3,4,6, 1,0, 1)    // i odd:  x buf1, prefetch -> buf0
        STEP(1,3,4,6, 0,2,5,7, 0,1, 1)    // i even: x buf0, prefetch -> buf1
    }
    STEP(0,2,5,7, 1,3,4,6, 1,0, 0)        // i = 511
#undef STEP
#undef XPREF
#undef XDOT

    // ---- Tail i=512: h1[511] from h0[511] (bufs 1,3) and h1[510] (bufs 4,6) ----
    {
        float e1a0=bj,e1a1=bj,e1a2=bj8,e1a3=bj8;
        float e1b0=0,e1b1=0,e1b2=0,e1b3=0;
        float e1c0=0,e1c1=0,e1c2=0,e1c3=0;
        float e1d0=0,e1d1=0,e1d2=0,e1d3=0;
        const float* B0h = HBf + 512;   const float* B0l = HBf + 3*512;
        const float* B1h = HBf + 4*512; const float* B1l = HBf + 6*512;
        #pragma unroll
        for (int t = 0; t < 8; t++) {
            unsigned bh0=__float_as_uint(B0h[o+64*t]);
            unsigned bh1=__float_as_uint(B0h[o+64*t+32]);
            unsigned bl0=__float_as_uint(B0l[o+64*t]);
            unsigned bl1=__float_as_uint(B0l[o+64*t+32]);
            uint4 l1 = *(const uint4*)&WLO[((4+w)*8+t)*128 + lane*4];
            if ((t&1)==0) { MMA3(e1a0,e1a1,e1a2,e1a3, &Ah1[4*t], l1, bh0,bh1, bl0,bl1) }
            else          { MMA3(e1b0,e1b1,e1b2,e1b3, &Ah1[4*t], l1, bh0,bh1, bl0,bl1) }
        }
        #pragma unroll
        for (int t = 0; t < 8; t++) {
            unsigned bh0=__float_as_uint(B1h[o+64*t]);
            unsigned bh1=__float_as_uint(B1h[o+64*t+32]);
            unsigned bl0=__float_as_uint(B1l[o+64*t]);
            unsigned bl1=__float_as_uint(B1l[o+64*t+32]);
            uint4 l2 = *(const uint4*)&WLO[((8+w)*8+t)*128 + lane*4];
            if ((t&1)==0) { MMA3(e1c0,e1c1,e1c2,e1c3, &Ah2[4*t], l2, bh0,bh1, bl0,bl1) }
            else          { MMA3(e1d0,e1d1,e1d2,e1d3, &Ah2[4*t], l2, bh0,bh1, bl0,bl1) }
        }
        h10 = fast_tanh_scaled(e1a0+e1b0+e1c0+e1d0);
        h11 = fast_tanh_scaled(e1a1+e1b1+e1c1+e1d1);
        h12 = fast_tanh_scaled(e1a2+e1b2+e1c2+e1d2);
        h13 = fast_tanh_scaled(e1a3+e1b3+e1c3+e1d3);
    }
#undef MMA3
#undef SSTORE

    // ---- FC: out[ce*8+e] = sum_j h1[511][j]*fc_w[j] + fc_b ----
    {
        float fw0 = fc_w[mb+g], fw8 = fc_w[mb+g+8];
        float p0 = h10*fw0 + h12*fw8;        // element e = 2tt
        float p1 = h11*fw0 + h13*fw8;        // element e = 2tt+1
        p0 += __shfl_xor_sync(FULLMASK,p0,4);  p1 += __shfl_xor_sync(FULLMASK,p1,4);
        p0 += __shfl_xor_sync(FULLMASK,p0,8);  p1 += __shfl_xor_sync(FULLMASK,p1,8);
        p0 += __shfl_xor_sync(FULLMASK,p0,16); p1 += __shfl_xor_sync(FULLMASK,p1,16);
        if (g == 0) { SFC[w*8 + 2*tt] = p0; SFC[w*8 + 2*tt + 1] = p1; }
        __syncthreads();
        if (tid < 8)
            out[ce*8 + tid] = SFC[tid] + SFC[8+tid] + SFC[16+tid] + SFC[24+tid] + fc_b[0];
    }
}

extern "C" void kernel_launch(void* const* d_in, const int* in_sizes, int n_in,
                              void* d_out, int out_size)
{
    const float* x     = (const float*)d_in[0];
    const float* W_ih0 = (const float*)d_in[1];
    const float* W_hh0 = (const float*)d_in[2];
    const float* b_ih0 = (const float*)d_in[3];
    const float* b_hh0 = (const float*)d_in[4];
    const float* W_ih1 = (const float*)d_in[5];
    const float* W_hh1 = (const float*)d_in[6];
    const float* b_ih1 = (const float*)d_in[7];
    const float* b_hh1 = (const float*)d_in[8];
    const float* fc_w  = (const float*)d_in[9];
    const float* fc_b  = (const float*)d_in[10];
    float* out = (float*)d_out;

    // smem: 12288 (WLO) + 4096 (HBf) + 32 (SFC) + 192 (SXF) unsigned = 66432 B
    const int smem_bytes = (12288 + 4096 + 32 + 192) * 4;
    cudaFuncSetAttribute(rnn_mma2_kernel,
                         cudaFuncAttributeMaxDynamicSharedMemorySize, smem_bytes);

    rnn_mma2_kernel<<<NCTA, 128, smem_bytes>>>(
        x, W_ih0, W_hh0, W_ih1, W_hh1,
        b_ih0, b_hh0, b_ih1, b_hh1, fc_w, fc_b, out);
}